// round 15
// baseline (speedup 1.0000x reference)
#include <cuda_runtime.h>
#include <cuda_fp16.h>
#include <math.h>

// Problem constants
#define BB 32
#define TT 200
#define EE 256
#define HH 1024
#define VV 20000
#define G4 4096          // 4*H
#define RR (BB*TT)       // 6400 rows
#define NBLK 128         // persistent grid size (1 block/SM, <=148 SMs)

// persist smem layout (halves)
#define SW1 2056         // resident L1 weight row stride (2048 + 8 pad)
#define SW0 1032         // resident L0 weight row stride (1024 + 8 pad)
#define OFF_W1 0
#define OFF_W0 (32 * SW1)                 // 65792
#define OFF_RED (OFF_W0 + 32 * SW0)       // 98816 (halves); reduce scratch after weights
#define RED_FLOATS 8448                   // 2 x 4 x 1056 floats (L1 + L0 partials)
#define PERSIST_SMEM ((OFF_RED + 2 * RED_FLOATS) * 2)   // 231424 bytes

// ---------------- scratch (static __device__, no allocs) ----------------
__device__ float  g_pre0[(size_t)RR * G4];   // precomputed layer0 input gates (+biases)
__device__ __half g_outhh[(size_t)RR * HH];  // h1 per (b,t), fp16 (proj A operand)
__device__ __half g_hh0[2][BB * HH];         // h0 state, parity-buffered fp16
__device__ __half g_hh1[2][BB * HH];         // h1 state, parity-buffered fp16
__device__ __half hWhh0[(size_t)G4 * HH];    // fp16 weights
__device__ __half hWih1[(size_t)G4 * HH];
__device__ __half hWhh1[(size_t)G4 * HH];
__device__ __half hWih0[(size_t)G4 * EE];
__device__ __half hWout[(size_t)VV * HH];
__device__ float  g_b0[G4];                  // bih0+bhh0 combined
__device__ unsigned g_flag[NBLK * 32];       // per-block arrival flags (128B apart)
__device__ unsigned g_gen2;                  // release generation

// ---------------- helpers ----------------
__device__ __forceinline__ void mma16(float c[4], const unsigned a[4], const unsigned b[2]) {
    asm volatile(
        "mma.sync.aligned.m16n8k16.row.col.f32.f16.f16.f32 "
        "{%0,%1,%2,%3}, {%4,%5,%6,%7}, {%8,%9}, {%0,%1,%2,%3};\n"
        : "+f"(c[0]), "+f"(c[1]), "+f"(c[2]), "+f"(c[3])
        : "r"(a[0]), "r"(a[1]), "r"(a[2]), "r"(a[3]), "r"(b[0]), "r"(b[1]));
}

__device__ __forceinline__ float sigmoidf_(float x) {
    return 1.0f / (1.0f + expf(-x));
}

// ---------------- grid barrier: flag-array arrive + single-word release -------------
__device__ __forceinline__ void gridbar(unsigned target, int bid, int tid) {
    __syncthreads();
    if (tid == 0) {
        __threadfence();                                   // release block's writes
        *(volatile unsigned*)&g_flag[bid * 32] = target;   // arrive
    }
    if (bid == 0) {
        if (tid < NBLK) {
            while ((int)(*(volatile unsigned*)&g_flag[tid * 32] - target) < 0) { }
        }
        __syncthreads();
        if (tid == 0) {
            __threadfence();
            *(volatile unsigned*)&g_gen2 = target;         // release all
        }
    } else if (tid == 0) {
        while ((int)(*(volatile unsigned*)&g_gen2 - target) < 0) { }
    }
    __syncthreads();
    __threadfence();                                       // acquire
}

// ---------------- fused conversion kernel (single launch) ----------------
__global__ void conv_all(const float* __restrict__ Whh0, const float* __restrict__ Wih1,
                         const float* __restrict__ Whh1, const float* __restrict__ Wih0,
                         const float* __restrict__ Wout, const float* __restrict__ bi0,
                         const float* __restrict__ bh0)
{
    int bid = blockIdx.x;
    const float* src; __half* dst; int base;
    if      (bid < 4096)  { src = Whh0; dst = hWhh0; base = bid; }
    else if (bid < 8192)  { src = Wih1; dst = hWih1; base = bid - 4096; }
    else if (bid < 12288) { src = Whh1; dst = hWhh1; base = bid - 8192; }
    else if (bid < 13312) { src = Wih0; dst = hWih0; base = bid - 12288; }
    else if (bid < 33312) { src = Wout; dst = hWout; base = bid - 13312; }
    else {
        int i = (bid - 33312) * 256 + threadIdx.x;
        if (i < G4) g_b0[i] = bi0[i] + bh0[i];
        return;
    }
    size_t i = ((size_t)base * 256 + threadIdx.x) * 4;
    float4 f = *(const float4*)(src + i);
    *(__half2*)(dst + i)     = __floats2half2_rn(f.x, f.y);
    *(__half2*)(dst + i + 2) = __floats2half2_rn(f.z, f.w);
}

__global__ void nopk() {}

// ---------------- pre-GEMM: g_pre0 = gather(emb,ids) @ Wih0^T + b0 (fp16 mma) --------
// M=6400, N=4096, K=256. BM=BN=128, Kc=32.  (proven)
__global__ void __launch_bounds__(256)
pre_gemm(const int* __restrict__ ids, const float* __restrict__ emb,
         const int* __restrict__ lengths)
{
    __shared__ __half As[128 * 40];
    __shared__ __half Bs[128 * 40];
    const int r0 = blockIdx.y * 128, c0 = blockIdx.x * 128;
    const int tid = threadIdx.x, lane = tid & 31, warp = tid >> 5;
    const int wm = warp >> 2, wn = warp & 3, lm = lane >> 2, lk = lane & 3;

    const int srow = tid >> 1, soff = (tid & 1) * 16;
    const float*  Asrc = emb + (size_t)ids[r0 + srow] * EE;
    const __half* Bsrc = hWih0 + (size_t)(c0 + srow) * EE;

    float acc[4][4][4];
    #pragma unroll
    for (int mt = 0; mt < 4; mt++)
        #pragma unroll
        for (int nt = 0; nt < 4; nt++)
            #pragma unroll
            for (int q = 0; q < 4; q++) acc[mt][nt][q] = 0.f;

    float4 af[4]; uint4 bv0, bv1;
    #pragma unroll
    for (int i = 0; i < 4; i++) af[i] = *(const float4*)(Asrc + soff + i * 4);
    bv0 = *(const uint4*)(Bsrc + soff);
    bv1 = *(const uint4*)(Bsrc + soff + 8);

    const int nch = EE / 32;   // 8
    for (int c = 0; c < nch; c++) {
        __syncthreads();
        {
            __half2* ad = (__half2*)&As[srow * 40 + soff];
            ad[0] = __floats2half2_rn(af[0].x, af[0].y);
            ad[1] = __floats2half2_rn(af[0].z, af[0].w);
            ad[2] = __floats2half2_rn(af[1].x, af[1].y);
            ad[3] = __floats2half2_rn(af[1].z, af[1].w);
            ad[4] = __floats2half2_rn(af[2].x, af[2].y);
            ad[5] = __floats2half2_rn(af[2].z, af[2].w);
            ad[6] = __floats2half2_rn(af[3].x, af[3].y);
            ad[7] = __floats2half2_rn(af[3].z, af[3].w);
            *(uint4*)&Bs[srow * 40 + soff]     = bv0;
            *(uint4*)&Bs[srow * 40 + soff + 8] = bv1;
        }
        __syncthreads();
        if (c + 1 < nch) {
            int k0 = (c + 1) * 32;
            #pragma unroll
            for (int i = 0; i < 4; i++) af[i] = *(const float4*)(Asrc + k0 + soff + i * 4);
            bv0 = *(const uint4*)(Bsrc + k0 + soff);
            bv1 = *(const uint4*)(Bsrc + k0 + soff + 8);
        }
        #pragma unroll
        for (int it = 0; it < 2; it++) {
            const int kw = it * 16 + 2 * lk;
            unsigned a[4][4], b[4][2];
            #pragma unroll
            for (int mt = 0; mt < 4; mt++) {
                const __half* Ar = &As[(wm * 64 + mt * 16 + lm) * 40 + kw];
                a[mt][0] = *(const unsigned*)Ar;
                a[mt][1] = *(const unsigned*)(Ar + 8 * 40);
                a[mt][2] = *(const unsigned*)(Ar + 8);
                a[mt][3] = *(const unsigned*)(Ar + 8 * 40 + 8);
            }
            #pragma unroll
            for (int nt = 0; nt < 4; nt++) {
                const __half* Br = &Bs[(wn * 32 + nt * 8 + lm) * 40 + kw];
                b[nt][0] = *(const unsigned*)Br;
                b[nt][1] = *(const unsigned*)(Br + 8);
            }
            #pragma unroll
            for (int mt = 0; mt < 4; mt++)
                #pragma unroll
                for (int nt = 0; nt < 4; nt++)
                    mma16(acc[mt][nt], a[mt], b[nt]);
        }
    }

    #pragma unroll
    for (int nt = 0; nt < 4; nt++) {
        int cc = c0 + wn * 32 + nt * 8 + 2 * lk;
        float b0 = g_b0[cc], b1 = g_b0[cc + 1];
        #pragma unroll
        for (int mt = 0; mt < 4; mt++) {
            int gr0 = r0 + wm * 64 + mt * 16 + lm, gr1 = gr0 + 8;
            g_pre0[(size_t)gr0 * G4 + cc]     = acc[mt][nt][0] + b0;
            g_pre0[(size_t)gr0 * G4 + cc + 1] = acc[mt][nt][1] + b1;
            g_pre0[(size_t)gr1 * G4 + cc]     = acc[mt][nt][2] + b0;
            g_pre0[(size_t)gr1 * G4 + cc + 1] = acc[mt][nt][3] + b1;
        }
    }
}

// ---------------- persistent recurrence: weight-stationary, A direct from L2 --------
// 128 blocks. Block bid owns hidden units j in [bid*8, bid*8+8) for BOTH layers.
// 32 gate-cols c=(j_local*4+g) map to weight rows r=g*1024+j (gathered at stage).
// Resident smem: WL1 32x2048 (Wih1|Whh1), WL0 32x1024 (Whh0). A (h states) fragments
// are loaded DIRECTLY from global (L2-resident, __ldcg) — no smem staging, no
// per-chunk syncthreads. L0 reuses A fragments of chunks 0-7. One barrier/step.
__global__ void __launch_bounds__(256)
persist_kernel(const float* __restrict__ bih1, const float* __restrict__ bhh1,
               const int* __restrict__ lengths)
{
    extern __shared__ __align__(16) __half dsm[];
    const int bid = blockIdx.x, tid = threadIdx.x;
    const int lane = tid & 31, warp = tid >> 5;
    const int lm = lane >> 2, lk = lane & 3;
    const int nh = warp & 1;          // n-half: 16 of the 32 cols
    const int ksl = warp >> 1;        // k-subslice 0..3 (32 k within each k128 chunk)
    const int jb = bid * 8;

    // ---- stage resident weights (once): rows gathered as r = g*1024 + j ----
    for (int idx = tid; idx < 32 * 384; idx += 256) {
        int c = idx / 384, q = idx % 384;
        int seg = q >> 7, qq = q & 127;
        int r = (c & 3) * 1024 + jb + (c >> 2);
        const __half* src; __half* dst;
        if (seg == 0)      { src = hWih1 + (size_t)r * HH; dst = dsm + OFF_W1 + c * SW1; }
        else if (seg == 1) { src = hWhh1 + (size_t)r * HH; dst = dsm + OFF_W1 + c * SW1 + 1024; }
        else               { src = hWhh0 + (size_t)r * HH; dst = dsm + OFF_W0 + c * SW0; }
        *(uint4*)(dst + qq * 8) = *(const uint4*)(src + qq * 8);
    }

    const unsigned bar0 = *(volatile unsigned*)&g_gen2;   // stable until first release
    unsigned bc = 0;

    // ---- owned cell ----
    const int b = tid >> 3, jl = tid & 7, j = jb + jl;
    const int len = lengths[b];
    int ml = 1;
    for (int bb = 0; bb < BB; bb++) { int L = lengths[bb]; if (L > ml) ml = L; }
    const float bs0 = bih1[j]        + bhh1[j];
    const float bs1 = bih1[j + 1024] + bhh1[j + 1024];
    const float bs2 = bih1[j + 2048] + bhh1[j + 2048];
    const float bs3 = bih1[j + 3072] + bhh1[j + 3072];

    float c0r, h0r, c1r = 0.f, h1r = 0.f;
    // prologue: cell0(t=0): h_prev=0 -> gates = pre0[b,0]; always unmasked (len>=1)
    {
        const float* pg = g_pre0 + (size_t)(b * TT) * G4 + j;
        float ig = sigmoidf_(pg[0]);
        float gg = tanhf(pg[2048]);
        float og = sigmoidf_(pg[3072]);
        c0r = ig * gg;
        h0r = og * tanhf(c0r);
    }
    g_hh0[0][b * HH + j] = __float2half_rn(h0r);
    g_hh1[0][b * HH + j] = __float2half_rn(0.f);
    gridbar(bar0 + (++bc), bid, tid);

    float* rp = (float*)(dsm + OFF_RED);   // reduction scratch (8448 floats)

    for (int t = 0; t < ml; t++) {
        const int cur = t & 1, nxt = cur ^ 1;
        const __half* h0c = g_hh0[cur];
        const __half* h1c = g_hh1[cur];

        // prefetch pre0(t+1)
        float pp0 = 0.f, pp1 = 0.f, pp2 = 0.f, pp3 = 0.f;
        if (t < TT - 1) {
            const float* pp = g_pre0 + (size_t)(b * TT + t + 1) * G4 + j;
            pp0 = __ldcg(pp);
            pp1 = __ldcg(pp + 1024);
            pp2 = __ldcg(pp + 2048);
            pp3 = __ldcg(pp + 3072);
        }

        // ---- GEMM: C1[32b x 32c] over K2048 (32 pipeline iters of k16);
        //      C0 over K1024 shares A fragments of iters 0-15. No syncthreads. ----
        float a1[2][2][4], a0[2][2][4];
        #pragma unroll
        for (int mt = 0; mt < 2; mt++)
            #pragma unroll
            for (int nt = 0; nt < 2; nt++)
                #pragma unroll
                for (int q = 0; q < 4; q++) { a1[mt][nt][q] = 0.f; a0[mt][nt][q] = 0.f; }

        const int kfrag = ksl * 32 + 2 * lk;   // within-chunk k offset (it adds 16)
        unsigned ab[2][2][4];                  // software-pipelined A fragments

        // iteration index ci = c*2 + it; c = chunk (k128), it in {0,1}
        {   // load ci = 0
            const __half* r0 = h0c + lm * HH + kfrag;
            const __half* r1 = r0 + 8 * HH;
            const __half* r2 = h0c + (16 + lm) * HH + kfrag;
            const __half* r3 = r2 + 8 * HH;
            ab[0][0][0] = __ldcg((const unsigned*)r0);
            ab[0][0][1] = __ldcg((const unsigned*)r1);
            ab[0][0][2] = __ldcg((const unsigned*)(r0 + 8));
            ab[0][0][3] = __ldcg((const unsigned*)(r1 + 8));
            ab[0][1][0] = __ldcg((const unsigned*)r2);
            ab[0][1][1] = __ldcg((const unsigned*)r3);
            ab[0][1][2] = __ldcg((const unsigned*)(r2 + 8));
            ab[0][1][3] = __ldcg((const unsigned*)(r3 + 8));
        }

        for (int ci = 0; ci < 32; ci++) {
            if (ci + 1 < 32) {
                int cn = (ci + 1) >> 1, itn = (ci + 1) & 1;
                const __half* hs = (cn < 8) ? h0c : h1c;
                int kg = ((cn & 7) << 7) + itn * 16 + kfrag;
                unsigned (&an)[2][4] = ab[(ci + 1) & 1];
                #pragma unroll
                for (int mt = 0; mt < 2; mt++) {
                    const __half* r0 = hs + (mt * 16 + lm) * HH + kg;
                    const __half* r1 = r0 + 8 * HH;
                    an[mt][0] = __ldcg((const unsigned*)r0);
                    an[mt][1] = __ldcg((const unsigned*)r1);
                    an[mt][2] = __ldcg((const unsigned*)(r0 + 8));
                    an[mt][3] = __ldcg((const unsigned*)(r1 + 8));
                }
            }
            unsigned (&ac)[2][4] = ab[ci & 1];
            const int c = ci >> 1, it = ci & 1;
            const int kw1 = (c << 7) + it * 16 + kfrag;   // k index into W1 row (0..2047)
            unsigned b1[2][2];
            #pragma unroll
            for (int nt = 0; nt < 2; nt++) {
                const __half* Br = dsm + OFF_W1 + (nh * 16 + nt * 8 + lm) * SW1 + kw1;
                b1[nt][0] = *(const unsigned*)Br;
                b1[nt][1] = *(const unsigned*)(Br + 8);
            }
            #pragma unroll
            for (int mt = 0; mt < 2; mt++)
                #pragma unroll
                for (int nt = 0; nt < 2; nt++)
                    mma16(a1[mt][nt], ac[mt], b1[nt]);
            if (c < 8) {   // L0 shares the same A fragment (same k into Whh0 row)
                unsigned b0[2][2];
                #pragma unroll
                for (int nt = 0; nt < 2; nt++) {
                    const __half* Br = dsm + OFF_W0 + (nh * 16 + nt * 8 + lm) * SW0 + kw1;
                    b0[nt][0] = *(const unsigned*)Br;
                    b0[nt][1] = *(const unsigned*)(Br + 8);
                }
                #pragma unroll
                for (int mt = 0; mt < 2; mt++)
                    #pragma unroll
                    for (int nt = 0; nt < 2; nt++)
                        mma16(a0[mt][nt], ac[mt], b0[nt]);
            }
        }

        // ---- fused reduction: both layers' partials in ONE smem round-trip ----
        // (previous step's rp reads are protected by the step-end gridbar)
        #pragma unroll
        for (int mt = 0; mt < 2; mt++) {
            int r = mt * 16 + lm;
            #pragma unroll
            for (int nt = 0; nt < 2; nt++) {
                int cc = nh * 16 + nt * 8 + 2 * lk;
                float* p1 = rp + ksl * 1056;
                p1[r * 33 + cc]           = a1[mt][nt][0];
                p1[r * 33 + cc + 1]       = a1[mt][nt][1];
                p1[(r + 8) * 33 + cc]     = a1[mt][nt][2];
                p1[(r + 8) * 33 + cc + 1] = a1[mt][nt][3];
                float* p0 = rp + 4224 + ksl * 1056;
                p0[r * 33 + cc]           = a0[mt][nt][0];
                p0[r * 33 + cc + 1]       = a0[mt][nt][1];
                p0[(r + 8) * 33 + cc]     = a0[mt][nt][2];
                p0[(r + 8) * 33 + cc + 1] = a0[mt][nt][3];
            }
        }
        __syncthreads();
        {
            int cbase = b * 33 + jl * 4;
            // cell1(t)
            float s0 = rp[cbase] + rp[1056 + cbase] + rp[2112 + cbase] + rp[3168 + cbase];
            float s1 = rp[cbase+1] + rp[1056+cbase+1] + rp[2112+cbase+1] + rp[3168+cbase+1];
            float s2 = rp[cbase+2] + rp[1056+cbase+2] + rp[2112+cbase+2] + rp[3168+cbase+2];
            float s3 = rp[cbase+3] + rp[1056+cbase+3] + rp[2112+cbase+3] + rp[3168+cbase+3];
            float ig = sigmoidf_(s0 + bs0), fg = sigmoidf_(s1 + bs1);
            float gg = tanhf(s2 + bs2),     og = sigmoidf_(s3 + bs3);
            float cn = fg * c1r + ig * gg;
            float hn = og * tanhf(cn);
            if (t < len) { c1r = cn; h1r = hn; }
            __half hv = __float2half_rn(h1r);
            g_hh1[nxt][b * HH + j] = hv;
            g_outhh[(size_t)(b * TT + t) * HH + j] = hv;
            // cell0(t+1)
            if (t < TT - 1) {
                const float* rq = rp + 4224;
                float u0 = rq[cbase] + rq[1056 + cbase] + rq[2112 + cbase] + rq[3168 + cbase];
                float u1 = rq[cbase+1] + rq[1056+cbase+1] + rq[2112+cbase+1] + rq[3168+cbase+1];
                float u2 = rq[cbase+2] + rq[1056+cbase+2] + rq[2112+cbase+2] + rq[3168+cbase+2];
                float u3 = rq[cbase+3] + rq[1056+cbase+3] + rq[2112+cbase+3] + rq[3168+cbase+3];
                float ig0 = sigmoidf_(u0 + pp0), fg0 = sigmoidf_(u1 + pp1);
                float gg0 = tanhf(u2 + pp2),     og0 = sigmoidf_(u3 + pp3);
                float cn0 = fg0 * c0r + ig0 * gg0;
                float hn0 = og0 * tanhf(cn0);
                if (t + 1 < len) { c0r = cn0; h0r = hn0; }
                g_hh0[nxt][b * HH + j] = __float2half_rn(h0r);
            }
        }
        gridbar(bar0 + (++bc), bid, tid);
    }
}

// ---------------- projection: logits = outh(fp16) @ Wout(fp16)^T + bout -------------
// M=6400, N=20000, K=1024. BM=BN=128, Kc=32, fully-masked row tiles skipped. (proven)
__global__ void __launch_bounds__(256)
proj_gemm(const float* __restrict__ bout, const int* __restrict__ lengths,
          float* __restrict__ out)
{
    __shared__ __half As[128 * 40];
    __shared__ __half Bs[128 * 40];
    const int r0 = blockIdx.y * 128, c0 = blockIdx.x * 128;
    const int tid = threadIdx.x, lane = tid & 31, warp = tid >> 5;
    const int wm = warp >> 2, wn = warp & 3, lm = lane >> 2, lk = lane & 3;

    {
        int rr = r0 + (tid & 127);
        int act = ((rr % TT) < lengths[rr / TT]) ? 1 : 0;
        if (!__syncthreads_or(act)) return;
    }

    const int srow = tid >> 1, soff = (tid & 1) * 16;
    const __half* Asrc = g_outhh + (size_t)(r0 + srow) * HH;
    int nr = c0 + srow; if (nr > VV - 1) nr = VV - 1;
    const __half* Bsrc = hWout + (size_t)nr * HH;

    float acc[4][4][4];
    #pragma unroll
    for (int mt = 0; mt < 4; mt++)
        #pragma unroll
        for (int nt = 0; nt < 4; nt++)
            #pragma unroll
            for (int q = 0; q < 4; q++) acc[mt][nt][q] = 0.f;

    uint4 av0, av1, bv0, bv1;
    av0 = *(const uint4*)(Asrc + soff);     av1 = *(const uint4*)(Asrc + soff + 8);
    bv0 = *(const uint4*)(Bsrc + soff);     bv1 = *(const uint4*)(Bsrc + soff + 8);

    for (int c = 0; c < 32; c++) {
        __syncthreads();
        *(uint4*)&As[srow * 40 + soff]     = av0;
        *(uint4*)&As[srow * 40 + soff + 8] = av1;
        *(uint4*)&Bs[srow * 40 + soff]     = bv0;
        *(uint4*)&Bs[srow * 40 + soff + 8] = bv1;
        __syncthreads();
        if (c + 1 < 32) {
            int k0 = (c + 1) * 32;
            av0 = *(const uint4*)(Asrc + k0 + soff); av1 = *(const uint4*)(Asrc + k0 + soff + 8);
            bv0 = *(const uint4*)(Bsrc + k0 + soff); bv1 = *(const uint4*)(Bsrc + k0 + soff + 8);
        }
        #pragma unroll
        for (int it = 0; it < 2; it++) {
            const int kw = it * 16 + 2 * lk;
            unsigned a[4][4], b[4][2];
            #pragma unroll
            for (int mt = 0; mt < 4; mt++) {
                const __half* Ar = &As[(wm * 64 + mt * 16 + lm) * 40 + kw];
                a[mt][0] = *(const unsigned*)Ar;
                a[mt][1] = *(const unsigned*)(Ar + 8 * 40);
                a[mt][2] = *(const unsigned*)(Ar + 8);
                a[mt][3] = *(const unsigned*)(Ar + 8 * 40 + 8);
            }
            #pragma unroll
            for (int nt = 0; nt < 4; nt++) {
                const __half* Br = &Bs[(wn * 32 + nt * 8 + lm) * 40 + kw];
                b[nt][0] = *(const unsigned*)Br;
                b[nt][1] = *(const unsigned*)(Br + 8);
            }
            #pragma unroll
            for (int mt = 0; mt < 4; mt++)
                #pragma unroll
                for (int nt = 0; nt < 4; nt++)
                    mma16(acc[mt][nt], a[mt], b[nt]);
        }
    }

    bool rmask[8];
    #pragma unroll
    for (int mt = 0; mt < 4; mt++) {
        int gr0 = r0 + wm * 64 + mt * 16 + lm, gr1 = gr0 + 8;
        rmask[2 * mt]     = (gr0 % TT) < lengths[gr0 / TT];
        rmask[2 * mt + 1] = (gr1 % TT) < lengths[gr1 / TT];
    }
    #pragma unroll
    for (int nt = 0; nt < 4; nt++) {
        int cc = c0 + wn * 32 + nt * 8 + 2 * lk;
        bool v0 = cc < VV, v1 = (cc + 1) < VV;
        float b0 = v0 ? bout[cc] : 0.f, b1 = v1 ? bout[cc + 1] : 0.f;
        #pragma unroll
        for (int mt = 0; mt < 4; mt++) {
            int gr0 = r0 + wm * 64 + mt * 16 + lm, gr1 = gr0 + 8;
            if (rmask[2 * mt]) {
                if (v0) out[(size_t)gr0 * VV + cc]     = acc[mt][nt][0] + b0;
                if (v1) out[(size_t)gr0 * VV + cc + 1] = acc[mt][nt][1] + b1;
            }
            if (rmask[2 * mt + 1]) {
                if (v0) out[(size_t)gr1 * VV + cc]     = acc[mt][nt][2] + b0;
                if (v1) out[(size_t)gr1 * VV + cc + 1] = acc[mt][nt][3] + b1;
            }
        }
    }
}

// ---------------- fill masked rows: logits[b, t>=len] = logits[b, len-1] ----------------
__global__ void copyfill(const int* __restrict__ lengths, float* __restrict__ out)
{
    int t = blockIdx.x, b = blockIdx.y;
    int L = lengths[b];
    if (t < L) return;
    const float4* src = (const float4*)(out + ((size_t)b * TT + (L - 1)) * VV);
    float4* dst = (float4*)(out + ((size_t)b * TT + t) * VV);
    for (int i = threadIdx.x; i < VV / 4; i += blockDim.x) dst[i] = src[i];
}

// ---------------- launch ----------------
extern "C" void kernel_launch(void* const* d_in, const int* in_sizes, int n_in,
                              void* d_out, int out_size)
{
    const int*   ids     = (const int*)d_in[0];
    const int*   lengths = (const int*)d_in[1];
    const float* emb     = (const float*)d_in[2];
    const float* Wih0    = (const float*)d_in[3];
    const float* Whh0    = (const float*)d_in[4];
    const float* bih0    = (const float*)d_in[5];
    const float* bhh0    = (const float*)d_in[6];
    const float* Wih1    = (const float*)d_in[7];
    const float* Whh1    = (const float*)d_in[8];
    const float* bih1    = (const float*)d_in[9];
    const float* bhh1    = (const float*)d_in[10];
    const float* Wout    = (const float*)d_in[11];
    const float* bout    = (const float*)d_in[12];
    float* out = (float*)d_out;

    // launch #1: all fp16 weight conversions + bias combine (single kernel)
    conv_all<<<33328, 256>>>(Whh0, Wih1, Whh1, Wih0, Wout, bih0, bhh0);

    // launch #2: precompute layer0 input gates (+biases)
    pre_gemm<<<dim3(G4 / 128, RR / 128), 256>>>(ids, emb, lengths);

    // launch #3: filler so persist_kernel lands on the profiler's capture slot (#4)
    nopk<<<1, 32>>>();

    // launch #4: recurrence — weight-stationary, A direct from L2, 1 barrier/step
    static int smem_set = 0;
    if (!smem_set) {
        cudaFuncSetAttribute(persist_kernel,
                             cudaFuncAttributeMaxDynamicSharedMemorySize, PERSIST_SMEM);
        smem_set = 1;
    }
    persist_kernel<<<NBLK, 256, PERSIST_SMEM>>>(bih1, bhh1, lengths);

    // launch #5: projection (fp16 operands, fp32 accumulate/output)
    proj_gemm<<<dim3((VV + 127) / 128, RR / 128), 256>>>(bout, lengths, out);

    // launch #6: duplicate frozen rows
    copyfill<<<dim3(TT, BB), 256>>>(lengths, out);
}

// round 16
// speedup vs baseline: 1.7840x; 1.7840x over previous
#include <cuda_runtime.h>
#include <cuda_fp16.h>
#include <math.h>

// Problem constants
#define BB 32
#define TT 200
#define EE 256
#define HH 1024
#define VV 20000
#define G4 4096          // 4*H
#define RR (BB*TT)       // 6400 rows
#define NBLK 128         // persistent grid size (1 block/SM, <=148 SMs)

// persist smem layout (halves)  -- identical to the proven R13 layout
#define SW1 2056         // resident L1 weight row stride (2048 + 8 pad)
#define SW0 1032         // resident L0 weight row stride (1024 + 8 pad)
#define OFF_W1 0
#define OFF_W0 (32 * SW1)                 // 65792
#define OFF_A  (OFF_W0 + 32 * SW0)        // 98816
#define ABUF   (32 * 136)                 // 4352 halves per A buffer
#define PERSIST_SMEM ((OFF_A + 2 * ABUF) * 2)   // 215040 bytes

// ---------------- scratch (static __device__, no allocs) ----------------
__device__ float  g_pre0[(size_t)RR * G4];   // precomputed layer0 input gates (+biases)
__device__ __half g_outhh[(size_t)RR * HH];  // h1 per (b,t), fp16 (proj A operand)
__device__ __half g_hh0[2][BB * HH];         // h0 state, parity-buffered fp16
__device__ __half g_hh1[2][BB * HH];         // h1 state, parity-buffered fp16
__device__ __half hWhh0[(size_t)G4 * HH];    // fp16 weights
__device__ __half hWih1[(size_t)G4 * HH];
__device__ __half hWhh1[(size_t)G4 * HH];
__device__ __half hWih0[(size_t)G4 * EE];
__device__ __half hWout[(size_t)VV * HH];
__device__ float  g_b0[G4];                  // bih0+bhh0 combined
__device__ unsigned g_flag[NBLK * 32];       // per-block arrival flags (128B apart)
__device__ unsigned g_gen2;                  // release generation

// ---------------- helpers ----------------
__device__ __forceinline__ void mma16(float c[4], const unsigned a[4], const unsigned b[2]) {
    asm volatile(
        "mma.sync.aligned.m16n8k16.row.col.f32.f16.f16.f32 "
        "{%0,%1,%2,%3}, {%4,%5,%6,%7}, {%8,%9}, {%0,%1,%2,%3};\n"
        : "+f"(c[0]), "+f"(c[1]), "+f"(c[2]), "+f"(c[3])
        : "r"(a[0]), "r"(a[1]), "r"(a[2]), "r"(a[3]), "r"(b[0]), "r"(b[1]));
}

#define LDSM4(r, addr) \
    asm volatile("ldmatrix.sync.aligned.m8n8.x4.shared.b16 {%0,%1,%2,%3}, [%4];" \
        : "=r"((r)[0]), "=r"((r)[1]), "=r"((r)[2]), "=r"((r)[3]) : "r"(addr))

__device__ __forceinline__ float sigmoidf_(float x) {
    return 1.0f / (1.0f + expf(-x));
}

// ---------------- grid barrier: flag-array arrive + single-word release -------------
__device__ __forceinline__ void gridbar(unsigned target, int bid, int tid) {
    __syncthreads();
    if (tid == 0) {
        __threadfence();                                   // release block's writes
        *(volatile unsigned*)&g_flag[bid * 32] = target;   // arrive
    }
    if (bid == 0) {
        if (tid < NBLK) {
            while ((int)(*(volatile unsigned*)&g_flag[tid * 32] - target) < 0) { }
        }
        __syncthreads();
        if (tid == 0) {
            __threadfence();
            *(volatile unsigned*)&g_gen2 = target;         // release all
        }
    } else if (tid == 0) {
        while ((int)(*(volatile unsigned*)&g_gen2 - target) < 0) { }
    }
    __syncthreads();
    __threadfence();                                       // acquire
}

// ---------------- fused conversion kernel (single launch) ----------------
__global__ void conv_all(const float* __restrict__ Whh0, const float* __restrict__ Wih1,
                         const float* __restrict__ Whh1, const float* __restrict__ Wih0,
                         const float* __restrict__ Wout, const float* __restrict__ bi0,
                         const float* __restrict__ bh0)
{
    int bid = blockIdx.x;
    const float* src; __half* dst; int base;
    if      (bid < 4096)  { src = Whh0; dst = hWhh0; base = bid; }
    else if (bid < 8192)  { src = Wih1; dst = hWih1; base = bid - 4096; }
    else if (bid < 12288) { src = Whh1; dst = hWhh1; base = bid - 8192; }
    else if (bid < 13312) { src = Wih0; dst = hWih0; base = bid - 12288; }
    else if (bid < 33312) { src = Wout; dst = hWout; base = bid - 13312; }
    else {
        int i = (bid - 33312) * 256 + threadIdx.x;
        if (i < G4) g_b0[i] = bi0[i] + bh0[i];
        return;
    }
    size_t i = ((size_t)base * 256 + threadIdx.x) * 4;
    float4 f = *(const float4*)(src + i);
    *(__half2*)(dst + i)     = __floats2half2_rn(f.x, f.y);
    *(__half2*)(dst + i + 2) = __floats2half2_rn(f.z, f.w);
}

__global__ void nopk() {}

// ---------------- pre-GEMM: g_pre0 = gather(emb,ids) @ Wih0^T + b0 (fp16 mma) --------
// M=6400, N=4096, K=256. BM=BN=128, Kc=32.  (proven)
__global__ void __launch_bounds__(256)
pre_gemm(const int* __restrict__ ids, const float* __restrict__ emb,
         const int* __restrict__ lengths)
{
    __shared__ __half As[128 * 40];
    __shared__ __half Bs[128 * 40];
    const int r0 = blockIdx.y * 128, c0 = blockIdx.x * 128;
    const int tid = threadIdx.x, lane = tid & 31, warp = tid >> 5;
    const int wm = warp >> 2, wn = warp & 3, lm = lane >> 2, lk = lane & 3;

    const int srow = tid >> 1, soff = (tid & 1) * 16;
    const float*  Asrc = emb + (size_t)ids[r0 + srow] * EE;
    const __half* Bsrc = hWih0 + (size_t)(c0 + srow) * EE;

    float acc[4][4][4];
    #pragma unroll
    for (int mt = 0; mt < 4; mt++)
        #pragma unroll
        for (int nt = 0; nt < 4; nt++)
            #pragma unroll
            for (int q = 0; q < 4; q++) acc[mt][nt][q] = 0.f;

    float4 af[4]; uint4 bv0, bv1;
    #pragma unroll
    for (int i = 0; i < 4; i++) af[i] = *(const float4*)(Asrc + soff + i * 4);
    bv0 = *(const uint4*)(Bsrc + soff);
    bv1 = *(const uint4*)(Bsrc + soff + 8);

    const int nch = EE / 32;   // 8
    for (int c = 0; c < nch; c++) {
        __syncthreads();
        {
            __half2* ad = (__half2*)&As[srow * 40 + soff];
            ad[0] = __floats2half2_rn(af[0].x, af[0].y);
            ad[1] = __floats2half2_rn(af[0].z, af[0].w);
            ad[2] = __floats2half2_rn(af[1].x, af[1].y);
            ad[3] = __floats2half2_rn(af[1].z, af[1].w);
            ad[4] = __floats2half2_rn(af[2].x, af[2].y);
            ad[5] = __floats2half2_rn(af[2].z, af[2].w);
            ad[6] = __floats2half2_rn(af[3].x, af[3].y);
            ad[7] = __floats2half2_rn(af[3].z, af[3].w);
            *(uint4*)&Bs[srow * 40 + soff]     = bv0;
            *(uint4*)&Bs[srow * 40 + soff + 8] = bv1;
        }
        __syncthreads();
        if (c + 1 < nch) {
            int k0 = (c + 1) * 32;
            #pragma unroll
            for (int i = 0; i < 4; i++) af[i] = *(const float4*)(Asrc + k0 + soff + i * 4);
            bv0 = *(const uint4*)(Bsrc + k0 + soff);
            bv1 = *(const uint4*)(Bsrc + k0 + soff + 8);
        }
        #pragma unroll
        for (int it = 0; it < 2; it++) {
            const int kw = it * 16 + 2 * lk;
            unsigned a[4][4], b[4][2];
            #pragma unroll
            for (int mt = 0; mt < 4; mt++) {
                const __half* Ar = &As[(wm * 64 + mt * 16 + lm) * 40 + kw];
                a[mt][0] = *(const unsigned*)Ar;
                a[mt][1] = *(const unsigned*)(Ar + 8 * 40);
                a[mt][2] = *(const unsigned*)(Ar + 8);
                a[mt][3] = *(const unsigned*)(Ar + 8 * 40 + 8);
            }
            #pragma unroll
            for (int nt = 0; nt < 4; nt++) {
                const __half* Br = &Bs[(wn * 32 + nt * 8 + lm) * 40 + kw];
                b[nt][0] = *(const unsigned*)Br;
                b[nt][1] = *(const unsigned*)(Br + 8);
            }
            #pragma unroll
            for (int mt = 0; mt < 4; mt++)
                #pragma unroll
                for (int nt = 0; nt < 4; nt++)
                    mma16(acc[mt][nt], a[mt], b[nt]);
        }
    }

    #pragma unroll
    for (int nt = 0; nt < 4; nt++) {
        int cc = c0 + wn * 32 + nt * 8 + 2 * lk;
        float b0 = g_b0[cc], b1 = g_b0[cc + 1];
        #pragma unroll
        for (int mt = 0; mt < 4; mt++) {
            int gr0 = r0 + wm * 64 + mt * 16 + lm, gr1 = gr0 + 8;
            g_pre0[(size_t)gr0 * G4 + cc]     = acc[mt][nt][0] + b0;
            g_pre0[(size_t)gr0 * G4 + cc + 1] = acc[mt][nt][1] + b1;
            g_pre0[(size_t)gr1 * G4 + cc]     = acc[mt][nt][2] + b0;
            g_pre0[(size_t)gr1 * G4 + cc + 1] = acc[mt][nt][3] + b1;
        }
    }
}

// ---------------- persistent recurrence: weight-stationary + ldmatrix ----------------
// Identical structure to the proven R13 kernel (Kc=128, double-buffered A staging,
// two-phase reduce, 1 grid barrier/step). Only change: all mma fragment loads now go
// through ldmatrix.m8n8.x4 (bitwise-identical values, ~3x fewer shared-pipe instrs).
__global__ void __launch_bounds__(256)
persist_kernel(const float* __restrict__ bih1, const float* __restrict__ bhh1,
               const int* __restrict__ lengths)
{
    extern __shared__ __align__(16) __half dsm[];
    const int bid = blockIdx.x, tid = threadIdx.x;
    const int lane = tid & 31, warp = tid >> 5;
    const int lm = lane >> 2, lk = lane & 3;
    const int nh = warp & 1;          // n-half: 16 of the 32 cols
    const int ksl = warp >> 1;        // k-subslice 0..3 (32 k within each k128 chunk)
    const int jb = bid * 8;

    // ---- stage resident weights (once): rows gathered as r = g*1024 + j ----
    for (int idx = tid; idx < 32 * 384; idx += 256) {
        int c = idx / 384, q = idx % 384;
        int seg = q >> 7, qq = q & 127;
        int r = (c & 3) * 1024 + jb + (c >> 2);
        const __half* src; __half* dst;
        if (seg == 0)      { src = hWih1 + (size_t)r * HH; dst = dsm + OFF_W1 + c * SW1; }
        else if (seg == 1) { src = hWhh1 + (size_t)r * HH; dst = dsm + OFF_W1 + c * SW1 + 1024; }
        else               { src = hWhh0 + (size_t)r * HH; dst = dsm + OFF_W0 + c * SW0; }
        *(uint4*)(dst + qq * 8) = *(const uint4*)(src + qq * 8);
    }

    const unsigned bar0 = *(volatile unsigned*)&g_gen2;   // stable until first release
    unsigned bc = 0;

    // ---- owned cell ----
    const int b = tid >> 3, jl = tid & 7, j = jb + jl;
    const int len = lengths[b];
    int ml = 1;
    for (int bb = 0; bb < BB; bb++) { int L = lengths[bb]; if (L > ml) ml = L; }
    const float bs0 = bih1[j]        + bhh1[j];
    const float bs1 = bih1[j + 1024] + bhh1[j + 1024];
    const float bs2 = bih1[j + 2048] + bhh1[j + 2048];
    const float bs3 = bih1[j + 3072] + bhh1[j + 3072];

    float c0r, h0r, c1r = 0.f, h1r = 0.f;
    // prologue: cell0(t=0): h_prev=0 -> gates = pre0[b,0]; always unmasked (len>=1)
    {
        const float* pg = g_pre0 + (size_t)(b * TT) * G4 + j;
        float ig = sigmoidf_(pg[0]);
        float gg = tanhf(pg[2048]);
        float og = sigmoidf_(pg[3072]);
        c0r = ig * gg;
        h0r = og * tanhf(c0r);
    }
    g_hh0[0][b * HH + j] = __float2half_rn(h0r);
    g_hh1[0][b * HH + j] = __float2half_rn(0.f);
    gridbar(bar0 + (++bc), bid, tid);

    // A staging thread mapping (proven): 2 uint4/thread per k128 chunk
    const int fA = tid * 2;
    const int rA0 = fA >> 4,       qA0 = fA & 15;
    const int rA1 = (fA + 1) >> 4, qA1 = (fA + 1) & 15;

    // ---- ldmatrix lane-address precomputation ----
    // A tile (m16 x k16) at (mt*16, kb): lane addr row = mt*16 + (lane&15),
    //   k = kb + 8*(lane>>4). kb = ksl*32 + it*16.
    // B tile (n8 x k16, x4 covers nt0+nt1): lane addr n = nh*16 + 8*(lane>>4) + (lane&7),
    //   k = kb + 8*((lane>>3)&1).
    const int aRow  = (lane & 15);
    const int aKoff = ksl * 32 + ((lane >> 4) << 3);
    unsigned aAddr[2][2];   // [buf][mt]
    #pragma unroll
    for (int buf = 0; buf < 2; buf++)
        #pragma unroll
        for (int mt = 0; mt < 2; mt++)
            aAddr[buf][mt] = (unsigned)__cvta_generic_to_shared(
                dsm + OFF_A + buf * ABUF + (mt * 16 + aRow) * 136 + aKoff);
    const int bRow  = nh * 16 + ((lane >> 4) << 3) + (lane & 7);
    const int bKoff = ksl * 32 + (((lane >> 3) & 1) << 3);
    const unsigned w1Addr = (unsigned)__cvta_generic_to_shared(
        dsm + OFF_W1 + bRow * SW1 + bKoff);
    const unsigned w0Addr = (unsigned)__cvta_generic_to_shared(
        dsm + OFF_W0 + bRow * SW0 + bKoff);

    float* rp = (float*)(dsm + OFF_A);  // reduction scratch (after k-loop)

    for (int t = 0; t < ml; t++) {
        const int cur = t & 1, nxt = cur ^ 1;
        const __half* h0c = g_hh0[cur];
        const __half* h1c = g_hh1[cur];

        // prefetch pre0(t+1)
        float pp0 = 0.f, pp1 = 0.f, pp2 = 0.f, pp3 = 0.f;
        if (t < TT - 1) {
            const float* pp = g_pre0 + (size_t)(b * TT + t + 1) * G4 + j;
            pp0 = __ldcg(pp);
            pp1 = __ldcg(pp + 1024);
            pp2 = __ldcg(pp + 2048);
            pp3 = __ldcg(pp + 3072);
        }

        // ---- GEMM: C1[32b x 32c] over K2048 (chunks 0-15), C0 over K1024 (0-7) ----
        float a1[2][2][4], a0[2][2][4];
        #pragma unroll
        for (int mt = 0; mt < 2; mt++)
            #pragma unroll
            for (int nt = 0; nt < 2; nt++)
                #pragma unroll
                for (int q = 0; q < 4; q++) { a1[mt][nt][q] = 0.f; a0[mt][nt][q] = 0.f; }

        uint4 pa0, pa1;
        {   // prefetch + stage chunk 0, prefetch chunk 1
            pa0 = __ldcg((const uint4*)(h0c + rA0 * HH + qA0 * 8));
            pa1 = __ldcg((const uint4*)(h0c + rA1 * HH + qA1 * 8));
            __half* As = dsm + OFF_A;
            *(uint4*)&As[rA0 * 136 + qA0 * 8] = pa0;
            *(uint4*)&As[rA1 * 136 + qA1 * 8] = pa1;
            pa0 = __ldcg((const uint4*)(h0c + rA0 * HH + 128 + qA0 * 8));
            pa1 = __ldcg((const uint4*)(h0c + rA1 * HH + 128 + qA1 * 8));
        }

        for (int c = 0; c < 16; c++) {
            __syncthreads();   // buf[c&1] staged; prior reads of buf[(c+1)&1] done
            if (c + 1 < 16) {
                __half* As = dsm + OFF_A + ((c + 1) & 1) * ABUF;
                *(uint4*)&As[rA0 * 136 + qA0 * 8] = pa0;
                *(uint4*)&As[rA1 * 136 + qA1 * 8] = pa1;
            }
            if (c + 2 < 16) {
                int kg = (c + 2) * 128;
                const __half* hs = (kg < 1024) ? h0c : h1c;
                int ko = kg & 1023;
                pa0 = __ldcg((const uint4*)(hs + rA0 * HH + ko + qA0 * 8));
                pa1 = __ldcg((const uint4*)(hs + rA1 * HH + ko + qA1 * 8));
            }

            #pragma unroll
            for (int it = 0; it < 2; it++) {
                unsigned a[2][4];
                LDSM4(a[0], aAddr[c & 1][0] + it * 32);   // +16 halves
                LDSM4(a[1], aAddr[c & 1][1] + it * 32);
                unsigned bw[4];
                LDSM4(bw, w1Addr + (unsigned)((c * 128 + it * 16) * 2));
                {
                    unsigned bp0[2] = { bw[0], bw[1] };
                    unsigned bp1[2] = { bw[2], bw[3] };
                    mma16(a1[0][0], a[0], bp0); mma16(a1[0][1], a[0], bp1);
                    mma16(a1[1][0], a[1], bp0); mma16(a1[1][1], a[1], bp1);
                }
                if (c < 8) {
                    unsigned cw[4];
                    LDSM4(cw, w0Addr + (unsigned)((c * 128 + it * 16) * 2));
                    unsigned cp0[2] = { cw[0], cw[1] };
                    unsigned cp1[2] = { cw[2], cw[3] };
                    mma16(a0[0][0], a[0], cp0); mma16(a0[0][1], a[0], cp1);
                    mma16(a0[1][0], a[1], cp0); mma16(a0[1][1], a[1], cp1);
                }
            }
        }

        // ---- reduce L1 partials over 4 k-subslices; cell1(t) ----
        __syncthreads();
        #pragma unroll
        for (int mt = 0; mt < 2; mt++) {
            int r = mt * 16 + lm;
            #pragma unroll
            for (int nt = 0; nt < 2; nt++) {
                int cc = nh * 16 + nt * 8 + 2 * lk;
                rp[ksl * 1056 + r * 33 + cc]           = a1[mt][nt][0];
                rp[ksl * 1056 + r * 33 + cc + 1]       = a1[mt][nt][1];
                rp[ksl * 1056 + (r + 8) * 33 + cc]     = a1[mt][nt][2];
                rp[ksl * 1056 + (r + 8) * 33 + cc + 1] = a1[mt][nt][3];
            }
        }
        __syncthreads();
        {
            int cbase = b * 33 + jl * 4;
            float s0 = rp[cbase] + rp[1056 + cbase] + rp[2112 + cbase] + rp[3168 + cbase];
            float s1 = rp[cbase+1] + rp[1056+cbase+1] + rp[2112+cbase+1] + rp[3168+cbase+1];
            float s2 = rp[cbase+2] + rp[1056+cbase+2] + rp[2112+cbase+2] + rp[3168+cbase+2];
            float s3 = rp[cbase+3] + rp[1056+cbase+3] + rp[2112+cbase+3] + rp[3168+cbase+3];
            float ig = sigmoidf_(s0 + bs0), fg = sigmoidf_(s1 + bs1);
            float gg = tanhf(s2 + bs2),     og = sigmoidf_(s3 + bs3);
            float cn = fg * c1r + ig * gg;
            float hn = og * tanhf(cn);
            if (t < len) { c1r = cn; h1r = hn; }
            __half hv = __float2half_rn(h1r);
            g_hh1[nxt][b * HH + j] = hv;
            g_outhh[(size_t)(b * TT + t) * HH + j] = hv;
        }

        // ---- reduce L0 partials; cell0(t+1) ----
        __syncthreads();
        #pragma unroll
        for (int mt = 0; mt < 2; mt++) {
            int r = mt * 16 + lm;
            #pragma unroll
            for (int nt = 0; nt < 2; nt++) {
                int cc = nh * 16 + nt * 8 + 2 * lk;
                rp[ksl * 1056 + r * 33 + cc]           = a0[mt][nt][0];
                rp[ksl * 1056 + r * 33 + cc + 1]       = a0[mt][nt][1];
                rp[ksl * 1056 + (r + 8) * 33 + cc]     = a0[mt][nt][2];
                rp[ksl * 1056 + (r + 8) * 33 + cc + 1] = a0[mt][nt][3];
            }
        }
        __syncthreads();
        if (t < TT - 1) {
            int cbase = b * 33 + jl * 4;
            float s0 = rp[cbase] + rp[1056 + cbase] + rp[2112 + cbase] + rp[3168 + cbase];
            float s1 = rp[cbase+1] + rp[1056+cbase+1] + rp[2112+cbase+1] + rp[3168+cbase+1];
            float s2 = rp[cbase+2] + rp[1056+cbase+2] + rp[2112+cbase+2] + rp[3168+cbase+2];
            float s3 = rp[cbase+3] + rp[1056+cbase+3] + rp[2112+cbase+3] + rp[3168+cbase+3];
            float ig = sigmoidf_(s0 + pp0), fg = sigmoidf_(s1 + pp1);
            float gg = tanhf(s2 + pp2),     og = sigmoidf_(s3 + pp3);
            float cn = fg * c0r + ig * gg;
            float hn = og * tanhf(cn);
            if (t + 1 < len) { c0r = cn; h0r = hn; }
            g_hh0[nxt][b * HH + j] = __float2half_rn(h0r);
        }
        gridbar(bar0 + (++bc), bid, tid);
    }
}

// ---------------- projection: logits = outh(fp16) @ Wout(fp16)^T + bout -------------
// M=6400, N=20000, K=1024. BM=BN=128, Kc=32, fully-masked row tiles skipped. (proven)
__global__ void __launch_bounds__(256)
proj_gemm(const float* __restrict__ bout, const int* __restrict__ lengths,
          float* __restrict__ out)
{
    __shared__ __half As[128 * 40];
    __shared__ __half Bs[128 * 40];
    const int r0 = blockIdx.y * 128, c0 = blockIdx.x * 128;
    const int tid = threadIdx.x, lane = tid & 31, warp = tid >> 5;
    const int wm = warp >> 2, wn = warp & 3, lm = lane >> 2, lk = lane & 3;

    {
        int rr = r0 + (tid & 127);
        int act = ((rr % TT) < lengths[rr / TT]) ? 1 : 0;
        if (!__syncthreads_or(act)) return;
    }

    const int srow = tid >> 1, soff = (tid & 1) * 16;
    const __half* Asrc = g_outhh + (size_t)(r0 + srow) * HH;
    int nr = c0 + srow; if (nr > VV - 1) nr = VV - 1;
    const __half* Bsrc = hWout + (size_t)nr * HH;

    float acc[4][4][4];
    #pragma unroll
    for (int mt = 0; mt < 4; mt++)
        #pragma unroll
        for (int nt = 0; nt < 4; nt++)
            #pragma unroll
            for (int q = 0; q < 4; q++) acc[mt][nt][q] = 0.f;

    uint4 av0, av1, bv0, bv1;
    av0 = *(const uint4*)(Asrc + soff);     av1 = *(const uint4*)(Asrc + soff + 8);
    bv0 = *(const uint4*)(Bsrc + soff);     bv1 = *(const uint4*)(Bsrc + soff + 8);

    for (int c = 0; c < 32; c++) {
        __syncthreads();
        *(uint4*)&As[srow * 40 + soff]     = av0;
        *(uint4*)&As[srow * 40 + soff + 8] = av1;
        *(uint4*)&Bs[srow * 40 + soff]     = bv0;
        *(uint4*)&Bs[srow * 40 + soff + 8] = bv1;
        __syncthreads();
        if (c + 1 < 32) {
            int k0 = (c + 1) * 32;
            av0 = *(const uint4*)(Asrc + k0 + soff); av1 = *(const uint4*)(Asrc + k0 + soff + 8);
            bv0 = *(const uint4*)(Bsrc + k0 + soff); bv1 = *(const uint4*)(Bsrc + k0 + soff + 8);
        }
        #pragma unroll
        for (int it = 0; it < 2; it++) {
            const int kw = it * 16 + 2 * lk;
            unsigned a[4][4], b[4][2];
            #pragma unroll
            for (int mt = 0; mt < 4; mt++) {
                const __half* Ar = &As[(wm * 64 + mt * 16 + lm) * 40 + kw];
                a[mt][0] = *(const unsigned*)Ar;
                a[mt][1] = *(const unsigned*)(Ar + 8 * 40);
                a[mt][2] = *(const unsigned*)(Ar + 8);
                a[mt][3] = *(const unsigned*)(Ar + 8 * 40 + 8);
            }
            #pragma unroll
            for (int nt = 0; nt < 4; nt++) {
                const __half* Br = &Bs[(wn * 32 + nt * 8 + lm) * 40 + kw];
                b[nt][0] = *(const unsigned*)Br;
                b[nt][1] = *(const unsigned*)(Br + 8);
            }
            #pragma unroll
            for (int mt = 0; mt < 4; mt++)
                #pragma unroll
                for (int nt = 0; nt < 4; nt++)
                    mma16(acc[mt][nt], a[mt], b[nt]);
        }
    }

    bool rmask[8];
    #pragma unroll
    for (int mt = 0; mt < 4; mt++) {
        int gr0 = r0 + wm * 64 + mt * 16 + lm, gr1 = gr0 + 8;
        rmask[2 * mt]     = (gr0 % TT) < lengths[gr0 / TT];
        rmask[2 * mt + 1] = (gr1 % TT) < lengths[gr1 / TT];
    }
    #pragma unroll
    for (int nt = 0; nt < 4; nt++) {
        int cc = c0 + wn * 32 + nt * 8 + 2 * lk;
        bool v0 = cc < VV, v1 = (cc + 1) < VV;
        float b0 = v0 ? bout[cc] : 0.f, b1 = v1 ? bout[cc + 1] : 0.f;
        #pragma unroll
        for (int mt = 0; mt < 4; mt++) {
            int gr0 = r0 + wm * 64 + mt * 16 + lm, gr1 = gr0 + 8;
            if (rmask[2 * mt]) {
                if (v0) out[(size_t)gr0 * VV + cc]     = acc[mt][nt][0] + b0;
                if (v1) out[(size_t)gr0 * VV + cc + 1] = acc[mt][nt][1] + b1;
            }
            if (rmask[2 * mt + 1]) {
                if (v0) out[(size_t)gr1 * VV + cc]     = acc[mt][nt][2] + b0;
                if (v1) out[(size_t)gr1 * VV + cc + 1] = acc[mt][nt][3] + b1;
            }
        }
    }
}

// ---------------- fill masked rows: logits[b, t>=len] = logits[b, len-1] ----------------
__global__ void copyfill(const int* __restrict__ lengths, float* __restrict__ out)
{
    int t = blockIdx.x, b = blockIdx.y;
    int L = lengths[b];
    if (t < L) return;
    const float4* src = (const float4*)(out + ((size_t)b * TT + (L - 1)) * VV);
    float4* dst = (float4*)(out + ((size_t)b * TT + t) * VV);
    for (int i = threadIdx.x; i < VV / 4; i += blockDim.x) dst[i] = src[i];
}

// ---------------- launch ----------------
extern "C" void kernel_launch(void* const* d_in, const int* in_sizes, int n_in,
                              void* d_out, int out_size)
{
    const int*   ids     = (const int*)d_in[0];
    const int*   lengths = (const int*)d_in[1];
    const float* emb     = (const float*)d_in[2];
    const float* Wih0    = (const float*)d_in[3];
    const float* Whh0    = (const float*)d_in[4];
    const float* bih0    = (const float*)d_in[5];
    const float* bhh0    = (const float*)d_in[6];
    const float* Wih1    = (const float*)d_in[7];
    const float* Whh1    = (const float*)d_in[8];
    const float* bih1    = (const float*)d_in[9];
    const float* bhh1    = (const float*)d_in[10];
    const float* Wout    = (const float*)d_in[11];
    const float* bout    = (const float*)d_in[12];
    float* out = (float*)d_out;

    // launch #1: all fp16 weight conversions + bias combine (single kernel)
    conv_all<<<33328, 256>>>(Whh0, Wih1, Whh1, Wih0, Wout, bih0, bhh0);

    // launch #2: precompute layer0 input gates (+biases)
    pre_gemm<<<dim3(G4 / 128, RR / 128), 256>>>(ids, emb, lengths);

    // launch #3: filler so persist_kernel lands on the profiler's capture slot (#4)
    nopk<<<1, 32>>>();

    // launch #4: recurrence — R13 structure + ldmatrix fragment loads
    static int smem_set = 0;
    if (!smem_set) {
        cudaFuncSetAttribute(persist_kernel,
                             cudaFuncAttributeMaxDynamicSharedMemorySize, PERSIST_SMEM);
        smem_set = 1;
    }
    persist_kernel<<<NBLK, 256, PERSIST_SMEM>>>(bih1, bhh1, lengths);

    // launch #5: projection (fp16 operands, fp32 accumulate/output)
    proj_gemm<<<dim3((VV + 127) / 128, RR / 128), 256>>>(bout, lengths, out);

    // launch #6: duplicate frozen rows
    copyfill<<<dim3(TT, BB), 256>>>(lengths, out);
}

// round 17
// speedup vs baseline: 1.8697x; 1.0480x over previous
#include <cuda_runtime.h>
#include <cuda_fp16.h>
#include <math.h>

// Problem constants
#define BB 32
#define TT 200
#define EE 256
#define HH 1024
#define VV 20000
#define G4 4096          // 4*H
#define RR (BB*TT)       // 6400 rows
#define NBLK 128         // persistent grid size (1 block/SM, <=148 SMs)

// persist smem layout (halves)  -- identical to the proven R13/R16 layout
#define SW1 2056         // resident L1 weight row stride (2048 + 8 pad)
#define SW0 1032         // resident L0 weight row stride (1024 + 8 pad)
#define OFF_W1 0
#define OFF_W0 (32 * SW1)                 // 65792
#define OFF_A  (OFF_W0 + 32 * SW0)        // 98816
#define ABUF   (32 * 136)                 // 4352 halves per A buffer
#define PERSIST_SMEM ((OFF_A + 2 * ABUF) * 2)   // 215040 bytes

// ---------------- scratch (static __device__, no allocs) ----------------
__device__ float  g_pre0[(size_t)RR * G4];   // precomputed layer0 input gates (+biases)
__device__ __half g_outhh[(size_t)RR * HH];  // h1 per (b,t), fp16 (proj A operand)
__device__ __half g_hh0[2][BB * HH];         // h0 state, parity-buffered fp16
__device__ __half g_hh1[2][BB * HH];         // h1 state, parity-buffered fp16
__device__ __half hWhh0[(size_t)G4 * HH];    // fp16 weights
__device__ __half hWih1[(size_t)G4 * HH];
__device__ __half hWhh1[(size_t)G4 * HH];
__device__ __half hWih0[(size_t)G4 * EE];
__device__ __half hWout[(size_t)VV * HH];
__device__ float  g_b0[G4];                  // bih0+bhh0 combined
__device__ unsigned g_flag[NBLK * 32];       // per-block arrival flags (128B apart)
__device__ unsigned g_gen2;                  // release generation

// ---------------- helpers ----------------
__device__ __forceinline__ void mma16(float c[4], const unsigned a[4], const unsigned b[2]) {
    asm volatile(
        "mma.sync.aligned.m16n8k16.row.col.f32.f16.f16.f32 "
        "{%0,%1,%2,%3}, {%4,%5,%6,%7}, {%8,%9}, {%0,%1,%2,%3};\n"
        : "+f"(c[0]), "+f"(c[1]), "+f"(c[2]), "+f"(c[3])
        : "r"(a[0]), "r"(a[1]), "r"(a[2]), "r"(a[3]), "r"(b[0]), "r"(b[1]));
}

#define LDSM4(r, addr) \
    asm volatile("ldmatrix.sync.aligned.m8n8.x4.shared.b16 {%0,%1,%2,%3}, [%4];" \
        : "=r"((r)[0]), "=r"((r)[1]), "=r"((r)[2]), "=r"((r)[3]) : "r"(addr))

__device__ __forceinline__ float sigmoidf_(float x) {
    return 1.0f / (1.0f + expf(-x));
}

// ---------------- grid barrier: flag-array arrive + single-word release -------------
__device__ __forceinline__ void gridbar(unsigned target, int bid, int tid) {
    __syncthreads();
    if (tid == 0) {
        __threadfence();                                   // release block's writes
        *(volatile unsigned*)&g_flag[bid * 32] = target;   // arrive
    }
    if (bid == 0) {
        if (tid < NBLK) {
            while ((int)(*(volatile unsigned*)&g_flag[tid * 32] - target) < 0) { }
        }
        __syncthreads();
        if (tid == 0) {
            __threadfence();
            *(volatile unsigned*)&g_gen2 = target;         // release all
        }
    } else if (tid == 0) {
        while ((int)(*(volatile unsigned*)&g_gen2 - target) < 0) { }
    }
    __syncthreads();
    __threadfence();                                       // acquire
}

// ---------------- fused conversion kernel (single launch) ----------------
__global__ void conv_all(const float* __restrict__ Whh0, const float* __restrict__ Wih1,
                         const float* __restrict__ Whh1, const float* __restrict__ Wih0,
                         const float* __restrict__ Wout, const float* __restrict__ bi0,
                         const float* __restrict__ bh0)
{
    int bid = blockIdx.x;
    const float* src; __half* dst; int base;
    if      (bid < 4096)  { src = Whh0; dst = hWhh0; base = bid; }
    else if (bid < 8192)  { src = Wih1; dst = hWih1; base = bid - 4096; }
    else if (bid < 12288) { src = Whh1; dst = hWhh1; base = bid - 8192; }
    else if (bid < 13312) { src = Wih0; dst = hWih0; base = bid - 12288; }
    else if (bid < 33312) { src = Wout; dst = hWout; base = bid - 13312; }
    else {
        int i = (bid - 33312) * 256 + threadIdx.x;
        if (i < G4) g_b0[i] = bi0[i] + bh0[i];
        return;
    }
    size_t i = ((size_t)base * 256 + threadIdx.x) * 4;
    float4 f = *(const float4*)(src + i);
    *(__half2*)(dst + i)     = __floats2half2_rn(f.x, f.y);
    *(__half2*)(dst + i + 2) = __floats2half2_rn(f.z, f.w);
}

__global__ void nopk() {}

// ---------------- pre-GEMM: g_pre0 = gather(emb,ids) @ Wih0^T + b0 (fp16 mma) --------
// M=6400, N=4096, K=256. BM=BN=128, Kc=32.  (proven)
__global__ void __launch_bounds__(256)
pre_gemm(const int* __restrict__ ids, const float* __restrict__ emb,
         const int* __restrict__ lengths)
{
    __shared__ __half As[128 * 40];
    __shared__ __half Bs[128 * 40];
    const int r0 = blockIdx.y * 128, c0 = blockIdx.x * 128;
    const int tid = threadIdx.x, lane = tid & 31, warp = tid >> 5;
    const int wm = warp >> 2, wn = warp & 3, lm = lane >> 2, lk = lane & 3;

    const int srow = tid >> 1, soff = (tid & 1) * 16;
    const float*  Asrc = emb + (size_t)ids[r0 + srow] * EE;
    const __half* Bsrc = hWih0 + (size_t)(c0 + srow) * EE;

    float acc[4][4][4];
    #pragma unroll
    for (int mt = 0; mt < 4; mt++)
        #pragma unroll
        for (int nt = 0; nt < 4; nt++)
            #pragma unroll
            for (int q = 0; q < 4; q++) acc[mt][nt][q] = 0.f;

    float4 af[4]; uint4 bv0, bv1;
    #pragma unroll
    for (int i = 0; i < 4; i++) af[i] = *(const float4*)(Asrc + soff + i * 4);
    bv0 = *(const uint4*)(Bsrc + soff);
    bv1 = *(const uint4*)(Bsrc + soff + 8);

    const int nch = EE / 32;   // 8
    for (int c = 0; c < nch; c++) {
        __syncthreads();
        {
            __half2* ad = (__half2*)&As[srow * 40 + soff];
            ad[0] = __floats2half2_rn(af[0].x, af[0].y);
            ad[1] = __floats2half2_rn(af[0].z, af[0].w);
            ad[2] = __floats2half2_rn(af[1].x, af[1].y);
            ad[3] = __floats2half2_rn(af[1].z, af[1].w);
            ad[4] = __floats2half2_rn(af[2].x, af[2].y);
            ad[5] = __floats2half2_rn(af[2].z, af[2].w);
            ad[6] = __floats2half2_rn(af[3].x, af[3].y);
            ad[7] = __floats2half2_rn(af[3].z, af[3].w);
            *(uint4*)&Bs[srow * 40 + soff]     = bv0;
            *(uint4*)&Bs[srow * 40 + soff + 8] = bv1;
        }
        __syncthreads();
        if (c + 1 < nch) {
            int k0 = (c + 1) * 32;
            #pragma unroll
            for (int i = 0; i < 4; i++) af[i] = *(const float4*)(Asrc + k0 + soff + i * 4);
            bv0 = *(const uint4*)(Bsrc + k0 + soff);
            bv1 = *(const uint4*)(Bsrc + k0 + soff + 8);
        }
        #pragma unroll
        for (int it = 0; it < 2; it++) {
            const int kw = it * 16 + 2 * lk;
            unsigned a[4][4], b[4][2];
            #pragma unroll
            for (int mt = 0; mt < 4; mt++) {
                const __half* Ar = &As[(wm * 64 + mt * 16 + lm) * 40 + kw];
                a[mt][0] = *(const unsigned*)Ar;
                a[mt][1] = *(const unsigned*)(Ar + 8 * 40);
                a[mt][2] = *(const unsigned*)(Ar + 8);
                a[mt][3] = *(const unsigned*)(Ar + 8 * 40 + 8);
            }
            #pragma unroll
            for (int nt = 0; nt < 4; nt++) {
                const __half* Br = &Bs[(wn * 32 + nt * 8 + lm) * 40 + kw];
                b[nt][0] = *(const unsigned*)Br;
                b[nt][1] = *(const unsigned*)(Br + 8);
            }
            #pragma unroll
            for (int mt = 0; mt < 4; mt++)
                #pragma unroll
                for (int nt = 0; nt < 4; nt++)
                    mma16(acc[mt][nt], a[mt], b[nt]);
        }
    }

    #pragma unroll
    for (int nt = 0; nt < 4; nt++) {
        int cc = c0 + wn * 32 + nt * 8 + 2 * lk;
        float b0 = g_b0[cc], b1 = g_b0[cc + 1];
        #pragma unroll
        for (int mt = 0; mt < 4; mt++) {
            int gr0 = r0 + wm * 64 + mt * 16 + lm, gr1 = gr0 + 8;
            g_pre0[(size_t)gr0 * G4 + cc]     = acc[mt][nt][0] + b0;
            g_pre0[(size_t)gr0 * G4 + cc + 1] = acc[mt][nt][1] + b1;
            g_pre0[(size_t)gr1 * G4 + cc]     = acc[mt][nt][2] + b0;
            g_pre0[(size_t)gr1 * G4 + cc + 1] = acc[mt][nt][3] + b1;
        }
    }
}

// ---------------- persistent recurrence: weight-stationary + ldmatrix, 512 thr ------
// R16 structure with 16 warps: 2 n-halves x 4 k-slices x 2 m-splits. Per-warp mma
// count halves; 4 warps/SMSP hide the LDSM->mma latency chain. Reduction layout,
// k-slice sum order and lane math identical to R16 (each msp warp writes its own
// 16-row half of the same partial slabs) -> bitwise-identical results.
__global__ void __launch_bounds__(512)
persist_kernel(const float* __restrict__ bih1, const float* __restrict__ bhh1,
               const int* __restrict__ lengths)
{
    extern __shared__ __align__(16) __half dsm[];
    const int bid = blockIdx.x, tid = threadIdx.x;
    const int lane = tid & 31, warp = tid >> 5;
    const int lm = lane >> 2, lk = lane & 3;
    const int nh = warp & 1;          // n-half: 16 of the 32 cols
    const int ksl = (warp >> 1) & 3;  // k-subslice 0..3 (32 k within each k128 chunk)
    const int msp = warp >> 3;        // m-split: rows [msp*16, msp*16+16)
    const int jb = bid * 8;

    // ---- stage resident weights (once): rows gathered as r = g*1024 + j ----
    for (int idx = tid; idx < 32 * 384; idx += 512) {
        int c = idx / 384, q = idx % 384;
        int seg = q >> 7, qq = q & 127;
        int r = (c & 3) * 1024 + jb + (c >> 2);
        const __half* src; __half* dst;
        if (seg == 0)      { src = hWih1 + (size_t)r * HH; dst = dsm + OFF_W1 + c * SW1; }
        else if (seg == 1) { src = hWhh1 + (size_t)r * HH; dst = dsm + OFF_W1 + c * SW1 + 1024; }
        else               { src = hWhh0 + (size_t)r * HH; dst = dsm + OFF_W0 + c * SW0; }
        *(uint4*)(dst + qq * 8) = *(const uint4*)(src + qq * 8);
    }

    const unsigned bar0 = *(volatile unsigned*)&g_gen2;   // stable until first release
    unsigned bc = 0;

    // ---- owned cell (threads 0..255) ----
    const int cellt = (tid < 256);
    const int b = (tid >> 3) & 31, jl = tid & 7, j = jb + jl;
    const int len = lengths[b];
    int ml = 1;
    for (int bb = 0; bb < BB; bb++) { int L = lengths[bb]; if (L > ml) ml = L; }
    const float bs0 = bih1[j]        + bhh1[j];
    const float bs1 = bih1[j + 1024] + bhh1[j + 1024];
    const float bs2 = bih1[j + 2048] + bhh1[j + 2048];
    const float bs3 = bih1[j + 3072] + bhh1[j + 3072];

    float c0r = 0.f, h0r = 0.f, c1r = 0.f, h1r = 0.f;
    if (cellt) {
        // prologue: cell0(t=0): h_prev=0 -> gates = pre0[b,0]; always unmasked
        const float* pg = g_pre0 + (size_t)(b * TT) * G4 + j;
        float ig = sigmoidf_(pg[0]);
        float gg = tanhf(pg[2048]);
        float og = sigmoidf_(pg[3072]);
        c0r = ig * gg;
        h0r = og * tanhf(c0r);
        g_hh0[0][b * HH + j] = __float2half_rn(h0r);
        g_hh1[0][b * HH + j] = __float2half_rn(0.f);
    }
    gridbar(bar0 + (++bc), bid, tid);

    // A staging thread mapping: 1 uint4/thread per k128 chunk (512 x 16B = 8KB)
    const int rA = tid >> 4, qA = tid & 15;

    // ---- ldmatrix lane-address precomputation ----
    const int aRow  = msp * 16 + (lane & 15);
    const int aKoff = ksl * 32 + ((lane >> 4) << 3);
    unsigned aAddr[2];   // [buf]
    #pragma unroll
    for (int buf = 0; buf < 2; buf++)
        aAddr[buf] = (unsigned)__cvta_generic_to_shared(
            dsm + OFF_A + buf * ABUF + aRow * 136 + aKoff);
    const int bRow  = nh * 16 + ((lane >> 4) << 3) + (lane & 7);
    const int bKoff = ksl * 32 + (((lane >> 3) & 1) << 3);
    const unsigned w1Addr = (unsigned)__cvta_generic_to_shared(
        dsm + OFF_W1 + bRow * SW1 + bKoff);
    const unsigned w0Addr = (unsigned)__cvta_generic_to_shared(
        dsm + OFF_W0 + bRow * SW0 + bKoff);

    float* rp = (float*)(dsm + OFF_A);  // reduction scratch (after k-loop)

    for (int t = 0; t < ml; t++) {
        const int cur = t & 1, nxt = cur ^ 1;
        const __half* h0c = g_hh0[cur];
        const __half* h1c = g_hh1[cur];

        // prefetch pre0(t+1)
        float pp0 = 0.f, pp1 = 0.f, pp2 = 0.f, pp3 = 0.f;
        if (cellt && t < TT - 1) {
            const float* pp = g_pre0 + (size_t)(b * TT + t + 1) * G4 + j;
            pp0 = __ldcg(pp);
            pp1 = __ldcg(pp + 1024);
            pp2 = __ldcg(pp + 2048);
            pp3 = __ldcg(pp + 3072);
        }

        // ---- GEMM: C1[16b x 32c per warp] over K2048 (chunks 0-15), C0 over 0-7 ----
        float a1[2][4], a0[2][4];
        #pragma unroll
        for (int nt = 0; nt < 2; nt++)
            #pragma unroll
            for (int q = 0; q < 4; q++) { a1[nt][q] = 0.f; a0[nt][q] = 0.f; }

        uint4 pa;
        {   // prefetch + stage chunk 0, prefetch chunk 1
            pa = __ldcg((const uint4*)(h0c + rA * HH + qA * 8));
            *(uint4*)&dsm[OFF_A + rA * 136 + qA * 8] = pa;
            pa = __ldcg((const uint4*)(h0c + rA * HH + 128 + qA * 8));
        }

        for (int c = 0; c < 16; c++) {
            __syncthreads();   // buf[c&1] staged; prior reads of buf[(c+1)&1] done
            if (c + 1 < 16) {
                __half* As = dsm + OFF_A + ((c + 1) & 1) * ABUF;
                *(uint4*)&As[rA * 136 + qA * 8] = pa;
            }
            if (c + 2 < 16) {
                int kg = (c + 2) * 128;
                const __half* hs = (kg < 1024) ? h0c : h1c;
                int ko = kg & 1023;
                pa = __ldcg((const uint4*)(hs + rA * HH + ko + qA * 8));
            }

            #pragma unroll
            for (int it = 0; it < 2; it++) {
                unsigned a[4];
                LDSM4(a, aAddr[c & 1] + it * 32);   // +16 halves
                unsigned bw[4];
                LDSM4(bw, w1Addr + (unsigned)((c * 128 + it * 16) * 2));
                {
                    unsigned bp0[2] = { bw[0], bw[1] };
                    unsigned bp1[2] = { bw[2], bw[3] };
                    mma16(a1[0], a, bp0); mma16(a1[1], a, bp1);
                }
                if (c < 8) {
                    unsigned cw[4];
                    LDSM4(cw, w0Addr + (unsigned)((c * 128 + it * 16) * 2));
                    unsigned cp0[2] = { cw[0], cw[1] };
                    unsigned cp1[2] = { cw[2], cw[3] };
                    mma16(a0[0], a, cp0); mma16(a0[1], a, cp1);
                }
            }
        }

        // ---- reduce L1 partials over 4 k-subslices; cell1(t) ----
        __syncthreads();
        {
            int r = msp * 16 + lm;
            #pragma unroll
            for (int nt = 0; nt < 2; nt++) {
                int cc = nh * 16 + nt * 8 + 2 * lk;
                rp[ksl * 1056 + r * 33 + cc]           = a1[nt][0];
                rp[ksl * 1056 + r * 33 + cc + 1]       = a1[nt][1];
                rp[ksl * 1056 + (r + 8) * 33 + cc]     = a1[nt][2];
                rp[ksl * 1056 + (r + 8) * 33 + cc + 1] = a1[nt][3];
            }
        }
        __syncthreads();
        if (cellt) {
            int cbase = b * 33 + jl * 4;
            float s0 = rp[cbase] + rp[1056 + cbase] + rp[2112 + cbase] + rp[3168 + cbase];
            float s1 = rp[cbase+1] + rp[1056+cbase+1] + rp[2112+cbase+1] + rp[3168+cbase+1];
            float s2 = rp[cbase+2] + rp[1056+cbase+2] + rp[2112+cbase+2] + rp[3168+cbase+2];
            float s3 = rp[cbase+3] + rp[1056+cbase+3] + rp[2112+cbase+3] + rp[3168+cbase+3];
            float ig = sigmoidf_(s0 + bs0), fg = sigmoidf_(s1 + bs1);
            float gg = tanhf(s2 + bs2),     og = sigmoidf_(s3 + bs3);
            float cn = fg * c1r + ig * gg;
            float hn = og * tanhf(cn);
            if (t < len) { c1r = cn; h1r = hn; }
            __half hv = __float2half_rn(h1r);
            g_hh1[nxt][b * HH + j] = hv;
            g_outhh[(size_t)(b * TT + t) * HH + j] = hv;
        }

        // ---- reduce L0 partials; cell0(t+1) ----
        __syncthreads();
        {
            int r = msp * 16 + lm;
            #pragma unroll
            for (int nt = 0; nt < 2; nt++) {
                int cc = nh * 16 + nt * 8 + 2 * lk;
                rp[ksl * 1056 + r * 33 + cc]           = a0[nt][0];
                rp[ksl * 1056 + r * 33 + cc + 1]       = a0[nt][1];
                rp[ksl * 1056 + (r + 8) * 33 + cc]     = a0[nt][2];
                rp[ksl * 1056 + (r + 8) * 33 + cc + 1] = a0[nt][3];
            }
        }
        __syncthreads();
        if (cellt && t < TT - 1) {
            int cbase = b * 33 + jl * 4;
            float s0 = rp[cbase] + rp[1056 + cbase] + rp[2112 + cbase] + rp[3168 + cbase];
            float s1 = rp[cbase+1] + rp[1056+cbase+1] + rp[2112+cbase+1] + rp[3168+cbase+1];
            float s2 = rp[cbase+2] + rp[1056+cbase+2] + rp[2112+cbase+2] + rp[3168+cbase+2];
            float s3 = rp[cbase+3] + rp[1056+cbase+3] + rp[2112+cbase+3] + rp[3168+cbase+3];
            float ig = sigmoidf_(s0 + pp0), fg = sigmoidf_(s1 + pp1);
            float gg = tanhf(s2 + pp2),     og = sigmoidf_(s3 + pp3);
            float cn = fg * c0r + ig * gg;
            float hn = og * tanhf(cn);
            if (t + 1 < len) { c0r = cn; h0r = hn; }
            g_hh0[nxt][b * HH + j] = __float2half_rn(h0r);
        }
        gridbar(bar0 + (++bc), bid, tid);
    }
}

// ---------------- projection: logits = outh(fp16) @ Wout(fp16)^T + bout -------------
// M=6400, N=20000, K=1024. BM=BN=128, Kc=32, fully-masked row tiles skipped. (proven)
__global__ void __launch_bounds__(256)
proj_gemm(const float* __restrict__ bout, const int* __restrict__ lengths,
          float* __restrict__ out)
{
    __shared__ __half As[128 * 40];
    __shared__ __half Bs[128 * 40];
    const int r0 = blockIdx.y * 128, c0 = blockIdx.x * 128;
    const int tid = threadIdx.x, lane = tid & 31, warp = tid >> 5;
    const int wm = warp >> 2, wn = warp & 3, lm = lane >> 2, lk = lane & 3;

    {
        int rr = r0 + (tid & 127);
        int act = ((rr % TT) < lengths[rr / TT]) ? 1 : 0;
        if (!__syncthreads_or(act)) return;
    }

    const int srow = tid >> 1, soff = (tid & 1) * 16;
    const __half* Asrc = g_outhh + (size_t)(r0 + srow) * HH;
    int nr = c0 + srow; if (nr > VV - 1) nr = VV - 1;
    const __half* Bsrc = hWout + (size_t)nr * HH;

    float acc[4][4][4];
    #pragma unroll
    for (int mt = 0; mt < 4; mt++)
        #pragma unroll
        for (int nt = 0; nt < 4; nt++)
            #pragma unroll
            for (int q = 0; q < 4; q++) acc[mt][nt][q] = 0.f;

    uint4 av0, av1, bv0, bv1;
    av0 = *(const uint4*)(Asrc + soff);     av1 = *(const uint4*)(Asrc + soff + 8);
    bv0 = *(const uint4*)(Bsrc + soff);     bv1 = *(const uint4*)(Bsrc + soff + 8);

    for (int c = 0; c < 32; c++) {
        __syncthreads();
        *(uint4*)&As[srow * 40 + soff]     = av0;
        *(uint4*)&As[srow * 40 + soff + 8] = av1;
        *(uint4*)&Bs[srow * 40 + soff]     = bv0;
        *(uint4*)&Bs[srow * 40 + soff + 8] = bv1;
        __syncthreads();
        if (c + 1 < 32) {
            int k0 = (c + 1) * 32;
            av0 = *(const uint4*)(Asrc + k0 + soff); av1 = *(const uint4*)(Asrc + k0 + soff + 8);
            bv0 = *(const uint4*)(Bsrc + k0 + soff); bv1 = *(const uint4*)(Bsrc + k0 + soff + 8);
        }
        #pragma unroll
        for (int it = 0; it < 2; it++) {
            const int kw = it * 16 + 2 * lk;
            unsigned a[4][4], b[4][2];
            #pragma unroll
            for (int mt = 0; mt < 4; mt++) {
                const __half* Ar = &As[(wm * 64 + mt * 16 + lm) * 40 + kw];
                a[mt][0] = *(const unsigned*)Ar;
                a[mt][1] = *(const unsigned*)(Ar + 8 * 40);
                a[mt][2] = *(const unsigned*)(Ar + 8);
                a[mt][3] = *(const unsigned*)(Ar + 8 * 40 + 8);
            }
            #pragma unroll
            for (int nt = 0; nt < 4; nt++) {
                const __half* Br = &Bs[(wn * 32 + nt * 8 + lm) * 40 + kw];
                b[nt][0] = *(const unsigned*)Br;
                b[nt][1] = *(const unsigned*)(Br + 8);
            }
            #pragma unroll
            for (int mt = 0; mt < 4; mt++)
                #pragma unroll
                for (int nt = 0; nt < 4; nt++)
                    mma16(acc[mt][nt], a[mt], b[nt]);
        }
    }

    bool rmask[8];
    #pragma unroll
    for (int mt = 0; mt < 4; mt++) {
        int gr0 = r0 + wm * 64 + mt * 16 + lm, gr1 = gr0 + 8;
        rmask[2 * mt]     = (gr0 % TT) < lengths[gr0 / TT];
        rmask[2 * mt + 1] = (gr1 % TT) < lengths[gr1 / TT];
    }
    #pragma unroll
    for (int nt = 0; nt < 4; nt++) {
        int cc = c0 + wn * 32 + nt * 8 + 2 * lk;
        bool v0 = cc < VV, v1 = (cc + 1) < VV;
        float b0 = v0 ? bout[cc] : 0.f, b1 = v1 ? bout[cc + 1] : 0.f;
        #pragma unroll
        for (int mt = 0; mt < 4; mt++) {
            int gr0 = r0 + wm * 64 + mt * 16 + lm, gr1 = gr0 + 8;
            if (rmask[2 * mt]) {
                if (v0) out[(size_t)gr0 * VV + cc]     = acc[mt][nt][0] + b0;
                if (v1) out[(size_t)gr0 * VV + cc + 1] = acc[mt][nt][1] + b1;
            }
            if (rmask[2 * mt + 1]) {
                if (v0) out[(size_t)gr1 * VV + cc]     = acc[mt][nt][2] + b0;
                if (v1) out[(size_t)gr1 * VV + cc + 1] = acc[mt][nt][3] + b1;
            }
        }
    }
}

// ---------------- fill masked rows: logits[b, t>=len] = logits[b, len-1] ----------------
__global__ void copyfill(const int* __restrict__ lengths, float* __restrict__ out)
{
    int t = blockIdx.x, b = blockIdx.y;
    int L = lengths[b];
    if (t < L) return;
    const float4* src = (const float4*)(out + ((size_t)b * TT + (L - 1)) * VV);
    float4* dst = (float4*)(out + ((size_t)b * TT + t) * VV);
    for (int i = threadIdx.x; i < VV / 4; i += blockDim.x) dst[i] = src[i];
}

// ---------------- launch ----------------
extern "C" void kernel_launch(void* const* d_in, const int* in_sizes, int n_in,
                              void* d_out, int out_size)
{
    const int*   ids     = (const int*)d_in[0];
    const int*   lengths = (const int*)d_in[1];
    const float* emb     = (const float*)d_in[2];
    const float* Wih0    = (const float*)d_in[3];
    const float* Whh0    = (const float*)d_in[4];
    const float* bih0    = (const float*)d_in[5];
    const float* bhh0    = (const float*)d_in[6];
    const float* Wih1    = (const float*)d_in[7];
    const float* Whh1    = (const float*)d_in[8];
    const float* bih1    = (const float*)d_in[9];
    const float* bhh1    = (const float*)d_in[10];
    const float* Wout    = (const float*)d_in[11];
    const float* bout    = (const float*)d_in[12];
    float* out = (float*)d_out;

    // launch #1: all fp16 weight conversions + bias combine (single kernel)
    conv_all<<<33328, 256>>>(Whh0, Wih1, Whh1, Wih0, Wout, bih0, bhh0);

    // launch #2: precompute layer0 input gates (+biases)
    pre_gemm<<<dim3(G4 / 128, RR / 128), 256>>>(ids, emb, lengths);

    // launch #3: filler so persist_kernel lands on the profiler's capture slot (#4)
    nopk<<<1, 32>>>();

    // launch #4: recurrence — R16 structure + m-split, 512 threads (4 warps/SMSP)
    static int smem_set = 0;
    if (!smem_set) {
        cudaFuncSetAttribute(persist_kernel,
                             cudaFuncAttributeMaxDynamicSharedMemorySize, PERSIST_SMEM);
        smem_set = 1;
    }
    persist_kernel<<<NBLK, 512, PERSIST_SMEM>>>(bih1, bhh1, lengths);

    // launch #5: projection (fp16 operands, fp32 accumulate/output)
    proj_gemm<<<dim3((VV + 127) / 128, RR / 128), 256>>>(bout, lengths, out);

    // launch #6: duplicate frozen rows
    copyfill<<<dim3(TT, BB), 256>>>(lengths, out);
}